// round 4
// baseline (speedup 1.0000x reference)
#include <cuda_runtime.h>
#include <math.h>

// Problem constants
#define E   1024
#define A   64
#define H   16
#define FFD 4096
#define B   2
#define S   2048
#define M   (B*S)
#define NQKV (3*E)

// ---------------- scratch (device globals) -----------------------------------
__device__ float g_x[M*E];
__device__ float g_wqkvT[E*NQKV];
__device__ float g_qkv[M*NQKV];
__device__ float g_q[H*B*S*A];
__device__ float g_attn[M*E];
__device__ float g_mha[M*E];
__device__ float g_hidden[M*FFD];
__device__ float g_ff[M*E];
__device__ float g_ffout[M*E];

// ---------------- elementwise add --------------------------------------------
__global__ void k_add(const float4* __restrict__ a, const float4* __restrict__ b,
                      float4* __restrict__ o) {
    int i = blockIdx.x * blockDim.x + threadIdx.x;
    float4 x = a[i], y = b[i];
    x.x += y.x; x.y += y.y; x.z += y.z; x.w += y.w;
    o[i] = x;
}

// ---------------- fuse Wq/Wk/Wv [H,E,A] -> [E, 3E] ---------------------------
__global__ void k_wqkv(const float* __restrict__ Wq, const float* __restrict__ Wk,
                       const float* __restrict__ Wv, float* __restrict__ out) {
    int idx = blockIdx.x * blockDim.x + threadIdx.x;
    int qkv = idx / (E*E);
    int rem = idx - qkv * (E*E);
    int h = rem / (E*A);
    int ea = rem - h * (E*A);
    int e = ea / A;
    int a = ea - e * A;
    const float* W = (qkv == 0) ? Wq : (qkv == 1) ? Wk : Wv;
    out[(size_t)e * NQKV + qkv * E + h * A + a] = W[rem];
}

// ---------------- tf32 tensor-core GEMM, fragment-packed smem ----------------
// 256 threads = 8 warps (2 M x 4 N), warp tile 64x32, mma.m16n8k8.tf32
// PA layout: [mtile(8)][kk(2)][lane(32)][slot(4)]  (slot = a0..a3 fragment regs)
// PB layout: [ntile(16)][kk(2)][lane(32)][slot(2)] (slot = b0..b1 fragment regs)

__device__ __forceinline__ float ftf32(float x) {
    float y;
    asm("cvt.rna.tf32.f32 %0, %1;" : "=f"(y) : "f"(x));
    return y;
}

__global__ __launch_bounds__(256, 2)
void k_gemm_tc(const float* __restrict__ Ag, const float* __restrict__ Bg,
               float* __restrict__ Cg, int Nd, int Kd,
               const float* __restrict__ bias, const float* __restrict__ resid,
               int do_relu) {
    __shared__ float PA[2][2048];   // 8*2*32*4
    __shared__ float PB[2][2048];   // 16*2*32*2

    int tid  = threadIdx.x;
    int lane = tid & 31, wid = tid >> 5;
    int wm = wid & 1, wn = wid >> 1;

    const float* Ab = Ag + (size_t)blockIdx.y * 128 * Kd;
    const float* Bb = Bg + blockIdx.x * 128;

    // global load mapping (same as before)
    int ar = tid >> 2;                 // A rows ar, ar+64
    int ac = (tid & 3) * 4;            // A k-cols (float4 at ac)
    int bk = tid >> 5;                 // B k-rows bk, bk+8
    int bc = (tid & 31) * 4;           // B n-cols (float4 at bc)

    // A packed-store base: value A[ar][ac+q] -> slot fixed, lane = (ar&7)*4 + q
    int a_mt = ar >> 4, a_r = ar & 15;
    int a_kk = ac >> 3;
    int a_slot = (a_r >> 3) + 2 * ((ac & 7) >> 2);
    int a_base = ((a_mt * 2 + a_kk) * 32 + (a_r & 7) * 4) * 4 + a_slot; // +qid*4
    // row ar+64 -> mtile +4 -> +1024 floats

    // B packed-store base: value B[bk(+8)][bc+j] -> lane = ((bc&7)+j)*4 + (bk&3)
    int b_nt = bc >> 3;
    int b_slot = bk >> 2;              // bk in 0..7
    int b_qid = bk & 3;
    int b_base = ((b_nt * 2 + 0) * 32 + (bc & 7) * 4 + b_qid) * 2 + b_slot; // +j*8
    // k-row bk+8 -> kk=1 -> +64 floats

    float acc[4][4][4];
#pragma unroll
    for (int i = 0; i < 4; i++)
#pragma unroll
        for (int j = 0; j < 4; j++)
#pragma unroll
            for (int r = 0; r < 4; r++) acc[i][j][r] = 0.f;

    float4 va0, va1, vb0, vb1;

#define STORE_TILE(bufi)                                                      \
    do {                                                                      \
        float* pa = &PA[bufi][a_base];                                        \
        pa[0]  = ftf32(va0.x); pa[4]  = ftf32(va0.y);                         \
        pa[8]  = ftf32(va0.z); pa[12] = ftf32(va0.w);                         \
        pa += 1024;                                                           \
        pa[0]  = ftf32(va1.x); pa[4]  = ftf32(va1.y);                         \
        pa[8]  = ftf32(va1.z); pa[12] = ftf32(va1.w);                         \
        float* pb = &PB[bufi][b_base];                                        \
        pb[0]  = ftf32(vb0.x); pb[8]  = ftf32(vb0.y);                         \
        pb[16] = ftf32(vb0.z); pb[24] = ftf32(vb0.w);                         \
        pb += 64;                                                             \
        pb[0]  = ftf32(vb1.x); pb[8]  = ftf32(vb1.y);                         \
        pb[16] = ftf32(vb1.z); pb[24] = ftf32(vb1.w);                         \
    } while (0)

    // prologue
    va0 = *(const float4*)(Ab + (size_t)ar * Kd + ac);
    va1 = *(const float4*)(Ab + (size_t)(ar + 64) * Kd + ac);
    vb0 = *(const float4*)(Bb + (size_t)bk * Nd + bc);
    vb1 = *(const float4*)(Bb + (size_t)(bk + 8) * Nd + bc);
    STORE_TILE(0);
    __syncthreads();

    int buf = 0;
    for (int k0 = 16; ; k0 += 16) {
        bool more = (k0 < Kd);
        if (more) {
            va0 = *(const float4*)(Ab + (size_t)ar * Kd + k0 + ac);
            va1 = *(const float4*)(Ab + (size_t)(ar + 64) * Kd + k0 + ac);
            vb0 = *(const float4*)(Bb + (size_t)(k0 + bk) * Nd + bc);
            vb1 = *(const float4*)(Bb + (size_t)(k0 + bk + 8) * Nd + bc);
        }
#pragma unroll
        for (int kk = 0; kk < 2; kk++) {
            float4 afv[4];
            float2 bfv[4];
#pragma unroll
            for (int mi = 0; mi < 4; mi++) {
                int mt = wm * 4 + mi;
                afv[mi] = *(const float4*)&PA[buf][((mt * 2 + kk) * 32 + lane) * 4];
            }
#pragma unroll
            for (int ni = 0; ni < 4; ni++) {
                int nt = wn * 4 + ni;
                bfv[ni] = *(const float2*)&PB[buf][((nt * 2 + kk) * 32 + lane) * 2];
            }
#pragma unroll
            for (int mi = 0; mi < 4; mi++)
#pragma unroll
                for (int ni = 0; ni < 4; ni++) {
                    asm volatile(
                        "mma.sync.aligned.m16n8k8.row.col.f32.tf32.tf32.f32 "
                        "{%0,%1,%2,%3}, {%4,%5,%6,%7}, {%8,%9}, {%0,%1,%2,%3};"
                        : "+f"(acc[mi][ni][0]), "+f"(acc[mi][ni][1]),
                          "+f"(acc[mi][ni][2]), "+f"(acc[mi][ni][3])
                        : "r"(__float_as_uint(afv[mi].x)),
                          "r"(__float_as_uint(afv[mi].y)),
                          "r"(__float_as_uint(afv[mi].z)),
                          "r"(__float_as_uint(afv[mi].w)),
                          "r"(__float_as_uint(bfv[ni].x)),
                          "r"(__float_as_uint(bfv[ni].y)));
                }
        }
        if (!more) break;
        int nb = buf ^ 1;
        STORE_TILE(nb);
        __syncthreads();
        buf = nb;
    }

    // epilogue
    int gid = lane >> 2, qid = lane & 3;
    int bn = blockIdx.x * 128;
#pragma unroll
    for (int mi = 0; mi < 4; mi++) {
        int r0 = blockIdx.y * 128 + wm * 64 + mi * 16 + gid;
        int r1 = r0 + 8;
#pragma unroll
        for (int ni = 0; ni < 4; ni++) {
            int col = bn + wn * 32 + ni * 8 + 2 * qid;
            float2 v0 = make_float2(acc[mi][ni][0], acc[mi][ni][1]);
            float2 v1 = make_float2(acc[mi][ni][2], acc[mi][ni][3]);
            if (bias) {
                float2 bb = *(const float2*)(bias + col);
                v0.x += bb.x; v0.y += bb.y; v1.x += bb.x; v1.y += bb.y;
            }
            if (resid) {
                float2 q0 = *(const float2*)(resid + (size_t)r0 * Nd + col);
                float2 q1 = *(const float2*)(resid + (size_t)r1 * Nd + col);
                v0.x += q0.x; v0.y += q0.y; v1.x += q1.x; v1.y += q1.y;
            }
            if (do_relu) {
                v0.x = fmaxf(v0.x, 0.f); v0.y = fmaxf(v0.y, 0.f);
                v1.x = fmaxf(v1.x, 0.f); v1.y = fmaxf(v1.y, 0.f);
            }
            *(float2*)(Cg + (size_t)r0 * Nd + col) = v0;
            *(float2*)(Cg + (size_t)r1 * Nd + col) = v1;
        }
    }
#undef STORE_TILE
}

// ---------------- scatter fused qkv -> Q scratch, K/V into d_out -------------
__global__ void k_scatter(const float* __restrict__ qkv, float* __restrict__ q,
                          float* __restrict__ kout, float* __restrict__ vout) {
    int idx = blockIdx.x * blockDim.x + threadIdx.x;
    int row = idx / NQKV;
    int col = idx - row * NQKV;
    int which = col / E;
    int cc = col - which * E;
    int h = cc / A;
    int a = cc - h * A;
    int b = row / S;
    int s = row - b * S;
    size_t dst = (((size_t)h * B + b) * S + s) * A + a;
    float v = qkv[(size_t)idx];
    float* d = (which == 0) ? q : (which == 1) ? kout : vout;
    d[dst] = v;
}

// ---------------- flash-style causal attention --------------------------------
#define ALD 68
#define ATTN_SMEM (4 * 64 * ALD * 4)

__global__ __launch_bounds__(256)
void k_attn(const float* __restrict__ Qg, const float* __restrict__ Kg,
            const float* __restrict__ Vg, float* __restrict__ attn_out) {
    extern __shared__ float sm[];
    float* Qs = sm;
    float* Ks = Qs + 64 * ALD;
    float* Vs = Ks + 64 * ALD;
    float* Ps = Vs + 64 * ALD;

    int hb = blockIdx.y;
    int qt = blockIdx.x;
    int h = hb / B, b = hb - h * B;
    int q0 = qt * 64;
    int tid = threadIdx.x;

    const float4* Q4 = (const float4*)(Qg + ((size_t)hb * S + q0) * A);
#pragma unroll
    for (int i = tid; i < 64 * 16; i += 256) {
        int r = i >> 4, c = i & 15;
        *(float4*)&Qs[r * ALD + c * 4] = Q4[i];
    }

    int r = tid >> 2;
    int g = tid & 3;
    int cbase = g * 16;
    float m_run = -INFINITY, l_run = 0.f;
    float acc[16];
#pragma unroll
    for (int i = 0; i < 16; i++) acc[i] = 0.f;

    int ntiles = qt + 1;
    int qidx = q0 + r;
    const float scale = 0.03125f;

    for (int t = 0; t < ntiles; t++) {
        int k0 = t * 64;
        __syncthreads();
        const float4* K4 = (const float4*)(Kg + ((size_t)hb * S + k0) * A);
        const float4* V4 = (const float4*)(Vg + ((size_t)hb * S + k0) * A);
#pragma unroll
        for (int i = tid; i < 64 * 16; i += 256) {
            int rr = i >> 4, cc = i & 15;
            *(float4*)&Ks[rr * ALD + cc * 4] = K4[i];
            *(float4*)&Vs[rr * ALD + cc * 4] = V4[i];
        }
        __syncthreads();

        float sv[16];
#pragma unroll
        for (int i = 0; i < 16; i++) sv[i] = 0.f;
        for (int k = 0; k < 64; k += 4) {
            float4 q4 = *(const float4*)&Qs[r * ALD + k];
#pragma unroll
            for (int i = 0; i < 16; i++) {
                float4 k4 = *(const float4*)&Ks[(cbase + i) * ALD + k];
                sv[i] += q4.x * k4.x + q4.y * k4.y + q4.z * k4.z + q4.w * k4.w;
            }
        }
        float mloc = -INFINITY;
#pragma unroll
        for (int i = 0; i < 16; i++) {
            int kidx = k0 + cbase + i;
            sv[i] = (kidx <= qidx) ? sv[i] * scale : -INFINITY;
            mloc = fmaxf(mloc, sv[i]);
        }
        mloc = fmaxf(mloc, __shfl_xor_sync(0xffffffff, mloc, 1));
        mloc = fmaxf(mloc, __shfl_xor_sync(0xffffffff, mloc, 2));
        float m_new = fmaxf(m_run, mloc);
        float alpha = __expf(m_run - m_new);

        float lloc = 0.f;
        float p[16];
#pragma unroll
        for (int i = 0; i < 16; i++) { p[i] = __expf(sv[i] - m_new); lloc += p[i]; }
        lloc += __shfl_xor_sync(0xffffffff, lloc, 1);
        lloc += __shfl_xor_sync(0xffffffff, lloc, 2);
        l_run = l_run * alpha + lloc;
        m_run = m_new;
#pragma unroll
        for (int i = 0; i < 16; i++) acc[i] *= alpha;
#pragma unroll
        for (int i = 0; i < 16; i++) Ps[r * ALD + cbase + i] = p[i];
        __syncthreads();

        for (int c = 0; c < 64; c++) {
            float pv = Ps[r * ALD + c];
            const float* vrow = &Vs[c * ALD + cbase];
            float4 v0 = *(const float4*)(vrow + 0);
            float4 v1 = *(const float4*)(vrow + 4);
            float4 v2 = *(const float4*)(vrow + 8);
            float4 v3 = *(const float4*)(vrow + 12);
            acc[0]  += pv * v0.x; acc[1]  += pv * v0.y; acc[2]  += pv * v0.z; acc[3]  += pv * v0.w;
            acc[4]  += pv * v1.x; acc[5]  += pv * v1.y; acc[6]  += pv * v1.z; acc[7]  += pv * v1.w;
            acc[8]  += pv * v2.x; acc[9]  += pv * v2.y; acc[10] += pv * v2.z; acc[11] += pv * v2.w;
            acc[12] += pv * v3.x; acc[13] += pv * v3.y; acc[14] += pv * v3.z; acc[15] += pv * v3.w;
        }
    }

    float inv_l = 1.f / l_run;
    int row = b * S + q0 + r;
    float* op = attn_out + (size_t)row * E + h * A + cbase;
#pragma unroll
    for (int i = 0; i < 16; i += 4) {
        float4 o4;
        o4.x = acc[i+0] * inv_l; o4.y = acc[i+1] * inv_l;
        o4.z = acc[i+2] * inv_l; o4.w = acc[i+3] * inv_l;
        *(float4*)(op + i) = o4;
    }
}

// ---------------- LayerNorm over rows of 1024 ---------------------------------
__global__ __launch_bounds__(256)
void k_ln(const float* __restrict__ a, const float* __restrict__ b,
          const float* __restrict__ gg, const float* __restrict__ bb,
          float* __restrict__ o) {
    __shared__ float red[16];
    __shared__ float s_mu, s_rstd;
    int row = blockIdx.x;
    int t = threadIdx.x;
    float4 x = ((const float4*)(a + (size_t)row * E))[t];
    if (b) {
        float4 y = ((const float4*)(b + (size_t)row * E))[t];
        x.x += y.x; x.y += y.y; x.z += y.z; x.w += y.w;
    }
    float sum = x.x + x.y + x.z + x.w;
    float sq  = x.x*x.x + x.y*x.y + x.z*x.z + x.w*x.w;
#pragma unroll
    for (int off = 16; off; off >>= 1) {
        sum += __shfl_xor_sync(0xffffffff, sum, off);
        sq  += __shfl_xor_sync(0xffffffff, sq,  off);
    }
    if ((t & 31) == 0) { red[t >> 5] = sum; red[8 + (t >> 5)] = sq; }
    __syncthreads();
    if (t == 0) {
        float ts = 0.f, tq = 0.f;
#pragma unroll
        for (int i = 0; i < 8; i++) { ts += red[i]; tq += red[8 + i]; }
        float mu = ts * (1.f / E);
        float var = tq * (1.f / E) - mu * mu;
        s_mu = mu; s_rstd = rsqrtf(var + 1e-5f);
    }
    __syncthreads();
    float mu = s_mu, rstd = s_rstd;
    float4 g4 = ((const float4*)gg)[t];
    float4 b4 = ((const float4*)bb)[t];
    float4 rr;
    rr.x = (x.x - mu) * rstd * g4.x + b4.x;
    rr.y = (x.y - mu) * rstd * g4.y + b4.y;
    rr.z = (x.z - mu) * rstd * g4.z + b4.z;
    rr.w = (x.w - mu) * rstd * g4.w + b4.w;
    ((float4*)(o + (size_t)row * E))[t] = rr;
}

// ---------------- launch -------------------------------------------------------
extern "C" void kernel_launch(void* const* d_in, const int* in_sizes, int n_in,
                              void* d_out, int out_size) {
    const float* emb    = (const float*)d_in[0];
    const float* pos    = (const float*)d_in[1];
    const float* Wq     = (const float*)d_in[2];
    const float* Wk     = (const float*)d_in[3];
    const float* Wv     = (const float*)d_in[4];
    const float* Wproj  = (const float*)d_in[5];
    const float* W1     = (const float*)d_in[6];
    const float* b1     = (const float*)d_in[7];
    const float* W2     = (const float*)d_in[8];
    const float* b2     = (const float*)d_in[9];
    const float* gattn  = (const float*)d_in[10];
    const float* beattn = (const float*)d_in[11];
    const float* gffn   = (const float*)d_in[12];
    const float* beffn  = (const float*)d_in[13];
    const float* gout   = (const float*)d_in[14];
    const float* beout  = (const float*)d_in[15];

    float* out  = (float*)d_out;
    float* Kout = out + (size_t)M * E;
    float* Vout = out + (size_t)2 * M * E;

    float *px, *pwT, *pqkv, *pq, *pattn, *pmha, *phid, *pff, *pffout;
    cudaGetSymbolAddress((void**)&px,    g_x);
    cudaGetSymbolAddress((void**)&pwT,   g_wqkvT);
    cudaGetSymbolAddress((void**)&pqkv,  g_qkv);
    cudaGetSymbolAddress((void**)&pq,    g_q);
    cudaGetSymbolAddress((void**)&pattn, g_attn);
    cudaGetSymbolAddress((void**)&pmha,  g_mha);
    cudaGetSymbolAddress((void**)&phid,  g_hidden);
    cudaGetSymbolAddress((void**)&pff,   g_ff);
    cudaGetSymbolAddress((void**)&pffout,g_ffout);

    cudaFuncSetAttribute(k_attn, cudaFuncAttributeMaxDynamicSharedMemorySize,
                         ATTN_SMEM);

    k_add<<<(M * E / 4) / 256, 256>>>((const float4*)emb, (const float4*)pos,
                                      (float4*)px);
    k_wqkv<<<(3 * E * E) / 256, 256>>>(Wq, Wk, Wv, pwT);
    {
        dim3 grid(NQKV / 128, M / 128);
        k_gemm_tc<<<grid, 256>>>(px, pwT, pqkv, NQKV, E, nullptr, nullptr, 0);
    }
    k_scatter<<<(M * NQKV) / 256, 256>>>(pqkv, pq, Kout, Vout);
    {
        dim3 grid(S / 64, H * B);
        k_attn<<<grid, 256, ATTN_SMEM>>>(pq, Kout, Vout, pattn);
    }
    {
        dim3 grid(E / 128, M / 128);
        k_gemm_tc<<<grid, 256>>>(pattn, Wproj, pqkv, E, E, nullptr, px, 0);
    }
    k_ln<<<M, 256>>>(pqkv, nullptr, gattn, beattn, pmha);
    {
        dim3 grid(FFD / 128, M / 128);
        k_gemm_tc<<<grid, 256>>>(pmha, W1, phid, FFD, E, b1, nullptr, 0);
    }
    {
        dim3 grid(E / 128, M / 128);
        k_gemm_tc<<<grid, 256>>>(phid, W2, pff, E, FFD, b2, nullptr, 1);
    }
    k_ln<<<M, 256>>>(pmha, pff, gffn, beffn, pffout);
    k_ln<<<M, 256>>>(pmha, pffout, gout, beout, out);
}

// round 5
// speedup vs baseline: 2.0871x; 2.0871x over previous
#include <cuda_runtime.h>
#include <math.h>

// Problem constants
#define E   1024
#define A   64
#define H   16
#define FFD 4096
#define B   2
#define S   2048
#define M   (B*S)
#define NQKV (3*E)

// ---------------- scratch (device globals) -----------------------------------
__device__ float g_x[M*E];
__device__ float g_wqkvT[E*NQKV];
__device__ float g_qkv[M*NQKV];
__device__ float g_q[H*B*S*A];
__device__ float g_attn[M*E];
__device__ float g_mha[M*E];
__device__ float g_hidden[M*FFD];
__device__ float g_ff[M*E];
__device__ float g_ffout[M*E];

// ---------------- elementwise add --------------------------------------------
__global__ void k_add(const float4* __restrict__ a, const float4* __restrict__ b,
                      float4* __restrict__ o) {
    int i = blockIdx.x * blockDim.x + threadIdx.x;
    float4 x = a[i], y = b[i];
    x.x += y.x; x.y += y.y; x.z += y.z; x.w += y.w;
    o[i] = x;
}

// ---------------- fuse Wq/Wk/Wv [H,E,A] -> [E, 3E] ---------------------------
__global__ void k_wqkv(const float* __restrict__ Wq, const float* __restrict__ Wk,
                       const float* __restrict__ Wv, float* __restrict__ out) {
    int idx = blockIdx.x * blockDim.x + threadIdx.x;
    int qkv = idx / (E*E);
    int rem = idx - qkv * (E*E);
    int h = rem / (E*A);
    int ea = rem - h * (E*A);
    int e = ea / A;
    int a = ea - e * A;
    const float* W = (qkv == 0) ? Wq : (qkv == 1) ? Wk : Wv;
    out[(size_t)e * NQKV + qkv * E + h * A + a] = W[rem];
}

// ---------------- tf32 tensor-core GEMM 128x128x16 (Round-3 core) ------------
#define GP 20
#define BP 136

__device__ __forceinline__ float ftf32(float x) {
    float y;
    asm("cvt.rna.tf32.f32 %0, %1;" : "=f"(y) : "f"(x));
    return y;
}

__global__ __launch_bounds__(256, 2)
void k_gemm_tc(const float* __restrict__ Ag, const float* __restrict__ Bg,
               float* __restrict__ Cg, int Nd, int Kd,
               const float* __restrict__ bias, const float* __restrict__ resid,
               int do_relu, int qkv_mode,
               float* __restrict__ qd, float* __restrict__ kd,
               float* __restrict__ vd) {
    __shared__ float As[2][128][GP];
    __shared__ float Bs[2][16][BP];

    int tid  = threadIdx.x;
    int lane = tid & 31, wid = tid >> 5;
    int wm = wid & 1, wn = wid >> 1;
    int gid = lane >> 2, qid = lane & 3;

    const float* Ab = Ag + (size_t)blockIdx.y * 128 * Kd;
    const float* Bb = Bg + blockIdx.x * 128;

    int ar = tid >> 2;
    int ac = (tid & 3) * 4;
    int bk = tid >> 5;
    int bc = (tid & 31) * 4;

    float acc[4][4][4];
#pragma unroll
    for (int i = 0; i < 4; i++)
#pragma unroll
        for (int j = 0; j < 4; j++)
#pragma unroll
            for (int r = 0; r < 4; r++) acc[i][j][r] = 0.f;

    float4 va0, va1, vb0, vb1;
    va0 = *(const float4*)(Ab + (size_t)ar * Kd + ac);
    va1 = *(const float4*)(Ab + (size_t)(ar + 64) * Kd + ac);
    vb0 = *(const float4*)(Bb + (size_t)bk * Nd + bc);
    vb1 = *(const float4*)(Bb + (size_t)(bk + 8) * Nd + bc);
    As[0][ar][ac+0] = ftf32(va0.x); As[0][ar][ac+1] = ftf32(va0.y);
    As[0][ar][ac+2] = ftf32(va0.z); As[0][ar][ac+3] = ftf32(va0.w);
    As[0][ar+64][ac+0] = ftf32(va1.x); As[0][ar+64][ac+1] = ftf32(va1.y);
    As[0][ar+64][ac+2] = ftf32(va1.z); As[0][ar+64][ac+3] = ftf32(va1.w);
    Bs[0][bk][bc+0] = ftf32(vb0.x); Bs[0][bk][bc+1] = ftf32(vb0.y);
    Bs[0][bk][bc+2] = ftf32(vb0.z); Bs[0][bk][bc+3] = ftf32(vb0.w);
    Bs[0][bk+8][bc+0] = ftf32(vb1.x); Bs[0][bk+8][bc+1] = ftf32(vb1.y);
    Bs[0][bk+8][bc+2] = ftf32(vb1.z); Bs[0][bk+8][bc+3] = ftf32(vb1.w);
    __syncthreads();

    int buf = 0;
    for (int k0 = 16; ; k0 += 16) {
        bool more = (k0 < Kd);
        if (more) {
            va0 = *(const float4*)(Ab + (size_t)ar * Kd + k0 + ac);
            va1 = *(const float4*)(Ab + (size_t)(ar + 64) * Kd + k0 + ac);
            vb0 = *(const float4*)(Bb + (size_t)(k0 + bk) * Nd + bc);
            vb1 = *(const float4*)(Bb + (size_t)(k0 + bk + 8) * Nd + bc);
        }
#pragma unroll
        for (int ks = 0; ks < 16; ks += 8) {
            unsigned af[4][4], bf[4][2];
#pragma unroll
            for (int mi = 0; mi < 4; mi++) {
                int row = wm * 64 + mi * 16 + gid;
                af[mi][0] = __float_as_uint(As[buf][row][ks + qid]);
                af[mi][1] = __float_as_uint(As[buf][row + 8][ks + qid]);
                af[mi][2] = __float_as_uint(As[buf][row][ks + qid + 4]);
                af[mi][3] = __float_as_uint(As[buf][row + 8][ks + qid + 4]);
            }
#pragma unroll
            for (int ni = 0; ni < 4; ni++) {
                int col = wn * 32 + ni * 8 + gid;
                bf[ni][0] = __float_as_uint(Bs[buf][ks + qid][col]);
                bf[ni][1] = __float_as_uint(Bs[buf][ks + qid + 4][col]);
            }
#pragma unroll
            for (int mi = 0; mi < 4; mi++)
#pragma unroll
                for (int ni = 0; ni < 4; ni++) {
                    asm volatile(
                        "mma.sync.aligned.m16n8k8.row.col.f32.tf32.tf32.f32 "
                        "{%0,%1,%2,%3}, {%4,%5,%6,%7}, {%8,%9}, {%0,%1,%2,%3};"
                        : "+f"(acc[mi][ni][0]), "+f"(acc[mi][ni][1]),
                          "+f"(acc[mi][ni][2]), "+f"(acc[mi][ni][3])
                        : "r"(af[mi][0]), "r"(af[mi][1]),
                          "r"(af[mi][2]), "r"(af[mi][3]),
                          "r"(bf[ni][0]), "r"(bf[ni][1]));
                }
        }
        if (!more) break;
        int nb = buf ^ 1;
        As[nb][ar][ac+0] = ftf32(va0.x); As[nb][ar][ac+1] = ftf32(va0.y);
        As[nb][ar][ac+2] = ftf32(va0.z); As[nb][ar][ac+3] = ftf32(va0.w);
        As[nb][ar+64][ac+0] = ftf32(va1.x); As[nb][ar+64][ac+1] = ftf32(va1.y);
        As[nb][ar+64][ac+2] = ftf32(va1.z); As[nb][ar+64][ac+3] = ftf32(va1.w);
        Bs[nb][bk][bc+0] = ftf32(vb0.x); Bs[nb][bk][bc+1] = ftf32(vb0.y);
        Bs[nb][bk][bc+2] = ftf32(vb0.z); Bs[nb][bk][bc+3] = ftf32(vb0.w);
        Bs[nb][bk+8][bc+0] = ftf32(vb1.x); Bs[nb][bk+8][bc+1] = ftf32(vb1.y);
        Bs[nb][bk+8][bc+2] = ftf32(vb1.z); Bs[nb][bk+8][bc+3] = ftf32(vb1.w);
        __syncthreads();
        buf = nb;
    }

    // epilogue
    int bn = blockIdx.x * 128;
#pragma unroll
    for (int mi = 0; mi < 4; mi++) {
        int r0 = blockIdx.y * 128 + wm * 64 + mi * 16 + gid;
        int r1 = r0 + 8;
#pragma unroll
        for (int ni = 0; ni < 4; ni++) {
            int col = bn + wn * 32 + ni * 8 + 2 * qid;
            float2 v0 = make_float2(acc[mi][ni][0], acc[mi][ni][1]);
            float2 v1 = make_float2(acc[mi][ni][2], acc[mi][ni][3]);
            if (qkv_mode) {
                // col -> (which, h, a); row -> (b, s). Write head-major [h,b,s,a].
                int which = col >> 10;
                int cc = col & 1023;
                int h = cc >> 6, a = cc & 63;
                int b = r0 >> 11;
                int s0r = r0 & 2047, s1r = r1 & 2047;
                float* basep = (which == 0) ? qd : (which == 1) ? kd : vd;
                size_t d0 = ((((size_t)h * B + b) * S + s0r) * A + a);
                size_t d1 = ((((size_t)h * B + b) * S + s1r) * A + a);
                *(float2*)(basep + d0) = v0;
                *(float2*)(basep + d1) = v1;
            } else {
                if (bias) {
                    float2 bb = *(const float2*)(bias + col);
                    v0.x += bb.x; v0.y += bb.y; v1.x += bb.x; v1.y += bb.y;
                }
                if (resid) {
                    float2 q0 = *(const float2*)(resid + (size_t)r0 * Nd + col);
                    float2 q1 = *(const float2*)(resid + (size_t)r1 * Nd + col);
                    v0.x += q0.x; v0.y += q0.y; v1.x += q1.x; v1.y += q1.y;
                }
                if (do_relu) {
                    v0.x = fmaxf(v0.x, 0.f); v0.y = fmaxf(v0.y, 0.f);
                    v1.x = fmaxf(v1.x, 0.f); v1.y = fmaxf(v1.y, 0.f);
                }
                *(float2*)(Cg + (size_t)r0 * Nd + col) = v0;
                *(float2*)(Cg + (size_t)r1 * Nd + col) = v1;
            }
        }
    }
}

// ---------------- flash-style causal attention, 2-row register blocking ------
// grid: (S/128, H*B), block 256. Each thread: rows r, r+64 of a 128-row Q tile,
// 16 score-columns (group g). P exchanged via warp shuffles (no smem P).
#define ALD 68
#define ATTN_SMEM ((128 + 64 + 64) * ALD * 4)

__global__ __launch_bounds__(256)
void k_attn(const float* __restrict__ Qg, const float* __restrict__ Kg,
            const float* __restrict__ Vg, float* __restrict__ attn_out) {
    extern __shared__ float sm[];
    float* Qs = sm;                    // 128 x ALD
    float* Ks = Qs + 128 * ALD;        // 64 x ALD
    float* Vs = Ks + 64 * ALD;         // 64 x ALD

    int hb = blockIdx.y;
    int qt = blockIdx.x;
    int h = hb / B, b = hb - h * B;
    int q0 = qt * 128;
    int tid = threadIdx.x;
    int lane = tid & 31;

    // load Q tile [128][64]
    const float4* Q4 = (const float4*)(Qg + ((size_t)hb * S + q0) * A);
#pragma unroll
    for (int i = tid; i < 128 * 16; i += 256) {
        int r = i >> 4, c = i & 15;
        *(float4*)&Qs[r * ALD + c * 4] = Q4[i];
    }

    int r = tid >> 2;
    int g = tid & 3;
    int cbase = g * 16;
    float m0 = -INFINITY, l0 = 0.f, m1 = -INFINITY, l1 = 0.f;
    float acc0[16], acc1[16];
#pragma unroll
    for (int i = 0; i < 16; i++) { acc0[i] = 0.f; acc1[i] = 0.f; }

    int ntl = 2 * qt + 2;
    int qi0 = q0 + r, qi1 = q0 + r + 64;
    const float scale = 0.03125f;   // 1/sqrt(E)

    for (int t = 0; t < ntl; t++) {
        int k0 = t * 64;
        __syncthreads();
        const float4* K4 = (const float4*)(Kg + ((size_t)hb * S + k0) * A);
        const float4* V4 = (const float4*)(Vg + ((size_t)hb * S + k0) * A);
#pragma unroll
        for (int i = tid; i < 64 * 16; i += 256) {
            int rr = i >> 4, cc = i & 15;
            *(float4*)&Ks[rr * ALD + cc * 4] = K4[i];
            *(float4*)&Vs[rr * ALD + cc * 4] = V4[i];
        }
        __syncthreads();

        // scores for both rows: K-tile reads shared across the 2 rows
        float sv0[16], sv1[16];
#pragma unroll
        for (int i = 0; i < 16; i++) { sv0[i] = 0.f; sv1[i] = 0.f; }
        for (int kc = 0; kc < 16; kc++) {
            float4 qa = *(const float4*)&Qs[r * ALD + kc * 4];
            float4 qb = *(const float4*)&Qs[(r + 64) * ALD + kc * 4];
#pragma unroll
            for (int i = 0; i < 16; i++) {
                float4 k4 = *(const float4*)&Ks[(cbase + i) * ALD + kc * 4];
                sv0[i] += qa.x * k4.x + qa.y * k4.y + qa.z * k4.z + qa.w * k4.w;
                sv1[i] += qb.x * k4.x + qb.y * k4.y + qb.z * k4.z + qb.w * k4.w;
            }
        }

        float ml0 = -INFINITY, ml1 = -INFINITY;
#pragma unroll
        for (int i = 0; i < 16; i++) {
            int kidx = k0 + cbase + i;
            sv0[i] = (kidx <= qi0) ? sv0[i] * scale : -INFINITY;
            sv1[i] = (kidx <= qi1) ? sv1[i] * scale : -INFINITY;
            ml0 = fmaxf(ml0, sv0[i]);
            ml1 = fmaxf(ml1, sv1[i]);
        }
        ml0 = fmaxf(ml0, __shfl_xor_sync(0xffffffff, ml0, 1));
        ml0 = fmaxf(ml0, __shfl_xor_sync(0xffffffff, ml0, 2));
        ml1 = fmaxf(ml1, __shfl_xor_sync(0xffffffff, ml1, 1));
        ml1 = fmaxf(ml1, __shfl_xor_sync(0xffffffff, ml1, 2));

        float mn0 = fmaxf(m0, ml0), mn1 = fmaxf(m1, ml1);
        float al0 = __expf(m0 - mn0), al1 = __expf(m1 - mn1);

        float p0[16], p1[16];
        float ll0 = 0.f, ll1 = 0.f;
#pragma unroll
        for (int i = 0; i < 16; i++) {
            p0[i] = __expf(sv0[i] - mn0); ll0 += p0[i];
            p1[i] = __expf(sv1[i] - mn1); ll1 += p1[i];
        }
        ll0 += __shfl_xor_sync(0xffffffff, ll0, 1);
        ll0 += __shfl_xor_sync(0xffffffff, ll0, 2);
        ll1 += __shfl_xor_sync(0xffffffff, ll1, 1);
        ll1 += __shfl_xor_sync(0xffffffff, ll1, 2);
        l0 = l0 * al0 + ll0;  m0 = mn0;
        l1 = l1 * al1 + ll1;  m1 = mn1;
#pragma unroll
        for (int i = 0; i < 16; i++) { acc0[i] *= al0; acc1[i] *= al1; }

        // PV: p-values exchanged over the 4 threads sharing each row
#pragma unroll
        for (int gp = 0; gp < 4; gp++) {
            int src = (lane & 28) | gp;
#pragma unroll
            for (int i = 0; i < 16; i++) {
                float pv0 = __shfl_sync(0xffffffff, p0[i], src);
                float pv1 = __shfl_sync(0xffffffff, p1[i], src);
                const float* vrow = &Vs[(gp * 16 + i) * ALD + cbase];
                float4 v0 = *(const float4*)(vrow + 0);
                float4 v1 = *(const float4*)(vrow + 4);
                float4 v2 = *(const float4*)(vrow + 8);
                float4 v3 = *(const float4*)(vrow + 12);
                acc0[0]  += pv0 * v0.x; acc0[1]  += pv0 * v0.y;
                acc0[2]  += pv0 * v0.z; acc0[3]  += pv0 * v0.w;
                acc0[4]  += pv0 * v1.x; acc0[5]  += pv0 * v1.y;
                acc0[6]  += pv0 * v1.z; acc0[7]  += pv0 * v1.w;
                acc0[8]  += pv0 * v2.x; acc0[9]  += pv0 * v2.y;
                acc0[10] += pv0 * v2.z; acc0[11] += pv0 * v2.w;
                acc0[12] += pv0 * v3.x; acc0[13] += pv0 * v3.y;
                acc0[14] += pv0 * v3.z; acc0[15] += pv0 * v3.w;
                acc1[0]  += pv1 * v0.x; acc1[1]  += pv1 * v0.y;
                acc1[2]  += pv1 * v0.z; acc1[3]  += pv1 * v0.w;
                acc1[4]  += pv1 * v1.x; acc1[5]  += pv1 * v1.y;
                acc1[6]  += pv1 * v1.z; acc1[7]  += pv1 * v1.w;
                acc1[8]  += pv1 * v2.x; acc1[9]  += pv1 * v2.y;
                acc1[10] += pv1 * v2.z; acc1[11] += pv1 * v2.w;
                acc1[12] += pv1 * v3.x; acc1[13] += pv1 * v3.y;
                acc1[14] += pv1 * v3.z; acc1[15] += pv1 * v3.w;
            }
        }
    }

    float il0 = 1.f / l0, il1 = 1.f / l1;
    int row0 = b * S + q0 + r;
    int row1 = row0 + 64;
    float* op0 = attn_out + (size_t)row0 * E + h * A + cbase;
    float* op1 = attn_out + (size_t)row1 * E + h * A + cbase;
#pragma unroll
    for (int i = 0; i < 16; i += 4) {
        float4 o0, o1;
        o0.x = acc0[i+0]*il0; o0.y = acc0[i+1]*il0;
        o0.z = acc0[i+2]*il0; o0.w = acc0[i+3]*il0;
        o1.x = acc1[i+0]*il1; o1.y = acc1[i+1]*il1;
        o1.z = acc1[i+2]*il1; o1.w = acc1[i+3]*il1;
        *(float4*)(op0 + i) = o0;
        *(float4*)(op1 + i) = o1;
    }
}

// ---------------- LayerNorm over rows of 1024 ---------------------------------
__global__ __launch_bounds__(256)
void k_ln(const float* __restrict__ a, const float* __restrict__ b,
          const float* __restrict__ gg, const float* __restrict__ bb,
          float* __restrict__ o) {
    __shared__ float red[16];
    __shared__ float s_mu, s_rstd;
    int row = blockIdx.x;
    int t = threadIdx.x;
    float4 x = ((const float4*)(a + (size_t)row * E))[t];
    if (b) {
        float4 y = ((const float4*)(b + (size_t)row * E))[t];
        x.x += y.x; x.y += y.y; x.z += y.z; x.w += y.w;
    }
    float sum = x.x + x.y + x.z + x.w;
    float sq  = x.x*x.x + x.y*x.y + x.z*x.z + x.w*x.w;
#pragma unroll
    for (int off = 16; off; off >>= 1) {
        sum += __shfl_xor_sync(0xffffffff, sum, off);
        sq  += __shfl_xor_sync(0xffffffff, sq,  off);
    }
    if ((t & 31) == 0) { red[t >> 5] = sum; red[8 + (t >> 5)] = sq; }
    __syncthreads();
    if (t == 0) {
        float ts = 0.f, tq = 0.f;
#pragma unroll
        for (int i = 0; i < 8; i++) { ts += red[i]; tq += red[8 + i]; }
        float mu = ts * (1.f / E);
        float var = tq * (1.f / E) - mu * mu;
        s_mu = mu; s_rstd = rsqrtf(var + 1e-5f);
    }
    __syncthreads();
    float mu = s_mu, rstd = s_rstd;
    float4 g4 = ((const float4*)gg)[t];
    float4 b4 = ((const float4*)bb)[t];
    float4 rr;
    rr.x = (x.x - mu) * rstd * g4.x + b4.x;
    rr.y = (x.y - mu) * rstd * g4.y + b4.y;
    rr.z = (x.z - mu) * rstd * g4.z + b4.z;
    rr.w = (x.w - mu) * rstd * g4.w + b4.w;
    ((float4*)(o + (size_t)row * E))[t] = rr;
}

// ---------------- launch -------------------------------------------------------
extern "C" void kernel_launch(void* const* d_in, const int* in_sizes, int n_in,
                              void* d_out, int out_size) {
    const float* emb    = (const float*)d_in[0];
    const float* pos    = (const float*)d_in[1];
    const float* Wq     = (const float*)d_in[2];
    const float* Wk     = (const float*)d_in[3];
    const float* Wv     = (const float*)d_in[4];
    const float* Wproj  = (const float*)d_in[5];
    const float* W1     = (const float*)d_in[6];
    const float* b1     = (const float*)d_in[7];
    const float* W2     = (const float*)d_in[8];
    const float* b2     = (const float*)d_in[9];
    const float* gattn  = (const float*)d_in[10];
    const float* beattn = (const float*)d_in[11];
    const float* gffn   = (const float*)d_in[12];
    const float* beffn  = (const float*)d_in[13];
    const float* gout   = (const float*)d_in[14];
    const float* beout  = (const float*)d_in[15];

    float* out  = (float*)d_out;
    float* Kout = out + (size_t)M * E;
    float* Vout = out + (size_t)2 * M * E;

    float *px, *pwT, *pqkv, *pq, *pattn, *pmha, *phid, *pff, *pffout;
    cudaGetSymbolAddress((void**)&px,    g_x);
    cudaGetSymbolAddress((void**)&pwT,   g_wqkvT);
    cudaGetSymbolAddress((void**)&pqkv,  g_qkv);
    cudaGetSymbolAddress((void**)&pq,    g_q);
    cudaGetSymbolAddress((void**)&pattn, g_attn);
    cudaGetSymbolAddress((void**)&pmha,  g_mha);
    cudaGetSymbolAddress((void**)&phid,  g_hidden);
    cudaGetSymbolAddress((void**)&pff,   g_ff);
    cudaGetSymbolAddress((void**)&pffout,g_ffout);

    cudaFuncSetAttribute(k_attn, cudaFuncAttributeMaxDynamicSharedMemorySize,
                         ATTN_SMEM);

    k_add<<<(M * E / 4) / 256, 256>>>((const float4*)emb, (const float4*)pos,
                                      (float4*)px);
    k_wqkv<<<(3 * E * E) / 256, 256>>>(Wq, Wk, Wv, pwT);
    // QKV gemm writes Q scratch + K/V d_out directly (scatter fused)
    {
        dim3 grid(NQKV / 128, M / 128);
        k_gemm_tc<<<grid, 256>>>(px, pwT, nullptr, NQKV, E, nullptr, nullptr, 0,
                                 1, pq, Kout, Vout);
    }
    {
        dim3 grid(S / 128, H * B);
        k_attn<<<grid, 256, ATTN_SMEM>>>(pq, Kout, Vout, pattn);
    }
    {
        dim3 grid(E / 128, M / 128);
        k_gemm_tc<<<grid, 256>>>(pattn, Wproj, pqkv, E, E, nullptr, px, 0,
                                 0, nullptr, nullptr, nullptr);
    }
    k_ln<<<M, 256>>>(pqkv, nullptr, gattn, beattn, pmha);
    {
        dim3 grid(FFD / 128, M / 128);
        k_gemm_tc<<<grid, 256>>>(pmha, W1, phid, FFD, E, b1, nullptr, 0,
                                 0, nullptr, nullptr, nullptr);
    }
    {
        dim3 grid(E / 128, M / 128);
        k_gemm_tc<<<grid, 256>>>(phid, W2, pff, E, FFD, b2, nullptr, 1,
                                 0, nullptr, nullptr, nullptr);
    }
    k_ln<<<M, 256>>>(pmha, pff, gffn, beffn, pffout);
    k_ln<<<M, 256>>>(pmha, pffout, gout, beout, out);
}

// round 8
// speedup vs baseline: 2.1818x; 1.0454x over previous
#include <cuda_runtime.h>
#include <math.h>
#include <stdint.h>

// Problem constants
#define E   1024
#define A   64
#define H   16
#define FFD 4096
#define B   2
#define S   2048
#define M   (B*S)
#define NQKV (3*E)

// ---------------- scratch (device globals) -----------------------------------
__device__ float g_x[M*E];           // full-precision x (residual)
__device__ float g_x32[M*E];         // tf32-rounded x (GEMM A)
__device__ float g_wqkv32[E*NQKV];   // fused tf32 [E][3E]
__device__ float g_wp32[E*E];        // tf32 Wproj [K][N]
__device__ float g_w132[E*FFD];      // tf32 W1
__device__ float g_w232[FFD*E];      // tf32 W2
__device__ float g_qkv[M*E];         // proj output scratch
__device__ float g_q[H*B*S*A];
__device__ float g_attn[M*E];        // tf32-rounded attention out
__device__ float g_mha[M*E];         // full mha (residuals)
__device__ float g_mha32[M*E];       // tf32 mha (FFN1 A)
__device__ float g_hidden[M*FFD];    // tf32-rounded hidden
__device__ float g_ff[M*E];
__device__ float g_ffout[M*E];

// ---------------- helpers -------------------------------------------------------
__device__ __forceinline__ float ftf32(float x) {
    float y;
    asm("cvt.rna.tf32.f32 %0, %1;" : "=f"(y) : "f"(x));
    return y;
}
__device__ __forceinline__ float4 ftf32_4(float4 v) {
    v.x = ftf32(v.x); v.y = ftf32(v.y); v.z = ftf32(v.z); v.w = ftf32(v.w);
    return v;
}
__device__ __forceinline__ uint32_t smem_u32(const void* p) {
    uint32_t r;
    asm("{ .reg .u64 t; cvta.to.shared.u64 t, %1; cvt.u32.u64 %0, t; }"
        : "=r"(r) : "l"(p));
    return r;
}
#define CP16(dst, src) \
    asm volatile("cp.async.cg.shared.global [%0], [%1], 16;" \
                 :: "r"(dst), "l"(src) : "memory")
#define CP_COMMIT() asm volatile("cp.async.commit_group;" ::: "memory")
#define CP_WAIT(n)  asm volatile("cp.async.wait_group %0;" :: "n"(n) : "memory")

// ---------------- x = emb + pos (full + tf32 copy) ------------------------------
__global__ void k_add(const float4* __restrict__ a, const float4* __restrict__ b,
                      float4* __restrict__ o, float4* __restrict__ o32) {
    int i = blockIdx.x * blockDim.x + threadIdx.x;
    float4 x = a[i], y = b[i];
    x.x += y.x; x.y += y.y; x.z += y.z; x.w += y.w;
    o[i] = x;
    o32[i] = ftf32_4(x);
}

// ---------------- fuse Wq/Wk/Wv [H,E,A] -> tf32 [E, 3E] -------------------------
__global__ void k_wqkv(const float* __restrict__ Wq, const float* __restrict__ Wk,
                       const float* __restrict__ Wv, float* __restrict__ out) {
    int idx = blockIdx.x * blockDim.x + threadIdx.x;
    int qkv = idx / (E*E);
    int rem = idx - qkv * (E*E);
    int h = rem / (E*A);
    int ea = rem - h * (E*A);
    int e = ea / A;
    int a = ea - e * A;
    const float* W = (qkv == 0) ? Wq : (qkv == 1) ? Wk : Wv;
    out[(size_t)e * NQKV + qkv * E + h * A + a] = ftf32(W[rem]);
}

// ---------------- tf32 convert proj/W1/W2 ----------------------------------------
#define WP4 (E*E/4)
#define W14 (E*FFD/4)
__global__ void k_wcvt(const float4* __restrict__ wp, const float4* __restrict__ w1,
                       const float4* __restrict__ w2, float4* __restrict__ op,
                       float4* __restrict__ o1, float4* __restrict__ o2) {
    int i = blockIdx.x * blockDim.x + threadIdx.x;
    if (i < WP4)                op[i] = ftf32_4(wp[i]);
    else if (i < WP4 + W14)     o1[i - WP4] = ftf32_4(w1[i - WP4]);
    else                        o2[i - WP4 - W14] = ftf32_4(w2[i - WP4 - W14]);
}

// ---------------- tf32 mma.sync GEMM, cp.async 3-stage ---------------------------
// A,B pre-rounded tf32 in gmem. A [Md][Kd], B [Kd][Nd]. Tile 128x128x16.
// smem stage: A 128x20 floats (pitch 20), B 16x136 floats (pitch 136).
#define STG_F 4736            // floats per stage (2560 + 2176)
#define GEMM_SMEM (3 * STG_F * 4)

__global__ __launch_bounds__(256, 2)
void k_gemm_tc(const float* __restrict__ Ag, const float* __restrict__ Bg,
               float* __restrict__ Cg, int Nd, int Kd,
               const float* __restrict__ bias, const float* __restrict__ resid,
               int do_relu, int out_tf32, int qkv_mode,
               float* __restrict__ qd, float* __restrict__ kd,
               float* __restrict__ vd) {
    extern __shared__ float smf[];
    uint32_t sb = smem_u32(smf);

    int tid = threadIdx.x;
    int lane = tid & 31, wid = tid >> 5;
    int wm = wid & 1, wn = wid >> 1;
    int gid = lane >> 2, qid = lane & 3;

    const float* Ab = Ag + (size_t)blockIdx.y * 128 * Kd;
    const float* Bb = Bg + blockIdx.x * 128;

    // 16B-chunk mapping: A tile 512 chunks, B tile 512 chunks; 2 each per thread
    int c1 = tid, c2 = tid + 256;
    int a1r = c1 >> 2, a1o = (c1 & 3) * 16, a1c = (c1 & 3) * 4;
    int a2r = c2 >> 2, a2o = (c2 & 3) * 16, a2c = (c2 & 3) * 4;
    int b1r = c1 >> 5, b1o = (c1 & 31) * 16, b1c = (c1 & 31) * 4;
    int b2r = c2 >> 5, b2o = (c2 & 31) * 16, b2c = (c2 & 31) * 4;

    float acc[4][4][4];
#pragma unroll
    for (int i = 0; i < 4; i++)
#pragma unroll
        for (int j = 0; j < 4; j++)
#pragma unroll
            for (int r = 0; r < 4; r++) acc[i][j][r] = 0.f;

    int nk = Kd >> 4;

#define LOAD_STAGE(s, k0)                                                     \
    do {                                                                      \
        uint32_t A0 = sb + (s) * (STG_F * 4);                                 \
        uint32_t B0 = A0 + 2560 * 4;                                          \
        CP16(A0 + a1r * 80 + a1o, Ab + (size_t)a1r * Kd + (k0) + a1c);        \
        CP16(A0 + a2r * 80 + a2o, Ab + (size_t)a2r * Kd + (k0) + a2c);        \
        CP16(B0 + b1r * 544 + b1o, Bb + (size_t)((k0) + b1r) * Nd + b1c);     \
        CP16(B0 + b2r * 544 + b2o, Bb + (size_t)((k0) + b2r) * Nd + b2c);     \
        CP_COMMIT();                                                          \
    } while (0)

    LOAD_STAGE(0, 0);
    LOAD_STAGE(1, 16);

    int buf = 0;
    for (int kc = 0; kc < nk; kc++) {
        if (kc + 2 < nk) { CP_WAIT(1); } else { CP_WAIT(0); }
        __syncthreads();
        if (kc + 2 < nk) {
            int s = (kc + 2) % 3;
            LOAD_STAGE(s, (kc + 2) * 16);
        }
        const float* As = smf + buf * STG_F;       // [128][20]
        const float* Bs = As + 2560;                // [16][136]
#pragma unroll
        for (int ks = 0; ks < 16; ks += 8) {
            unsigned af[4][4], bf[4][2];
#pragma unroll
            for (int mi = 0; mi < 4; mi++) {
                int row = wm * 64 + mi * 16 + gid;
                af[mi][0] = __float_as_uint(As[row * 20 + ks + qid]);
                af[mi][1] = __float_as_uint(As[(row + 8) * 20 + ks + qid]);
                af[mi][2] = __float_as_uint(As[row * 20 + ks + qid + 4]);
                af[mi][3] = __float_as_uint(As[(row + 8) * 20 + ks + qid + 4]);
            }
#pragma unroll
            for (int ni = 0; ni < 4; ni++) {
                int col = wn * 32 + ni * 8 + gid;
                bf[ni][0] = __float_as_uint(Bs[(ks + qid) * 136 + col]);
                bf[ni][1] = __float_as_uint(Bs[(ks + qid + 4) * 136 + col]);
            }
#pragma unroll
            for (int mi = 0; mi < 4; mi++)
#pragma unroll
                for (int ni = 0; ni < 4; ni++) {
                    asm volatile(
                        "mma.sync.aligned.m16n8k8.row.col.f32.tf32.tf32.f32 "
                        "{%0,%1,%2,%3}, {%4,%5,%6,%7}, {%8,%9}, {%0,%1,%2,%3};"
                        : "+f"(acc[mi][ni][0]), "+f"(acc[mi][ni][1]),
                          "+f"(acc[mi][ni][2]), "+f"(acc[mi][ni][3])
                        : "r"(af[mi][0]), "r"(af[mi][1]),
                          "r"(af[mi][2]), "r"(af[mi][3]),
                          "r"(bf[ni][0]), "r"(bf[ni][1]));
                }
        }
        buf = (buf + 1) % 3;
    }
#undef LOAD_STAGE

    // epilogue
    int bn = blockIdx.x * 128;
#pragma unroll
    for (int mi = 0; mi < 4; mi++) {
        int r0 = blockIdx.y * 128 + wm * 64 + mi * 16 + gid;
        int r1 = r0 + 8;
#pragma unroll
        for (int ni = 0; ni < 4; ni++) {
            int col = bn + wn * 32 + ni * 8 + 2 * qid;
            float2 v0 = make_float2(acc[mi][ni][0], acc[mi][ni][1]);
            float2 v1 = make_float2(acc[mi][ni][2], acc[mi][ni][3]);
            if (qkv_mode) {
                int which = col >> 10;
                int cc = col & 1023;
                int hh = cc >> 6, aa = cc & 63;
                int bb = r0 >> 11;
                int s0r = r0 & 2047, s1r = r1 & 2047;
                float* basep = (which == 0) ? qd : (which == 1) ? kd : vd;
                size_t d0 = ((((size_t)hh * B + bb) * S + s0r) * A + aa);
                size_t d1 = ((((size_t)hh * B + bb) * S + s1r) * A + aa);
                *(float2*)(basep + d0) = v0;
                *(float2*)(basep + d1) = v1;
            } else {
                if (bias) {
                    float2 bv = *(const float2*)(bias + col);
                    v0.x += bv.x; v0.y += bv.y; v1.x += bv.x; v1.y += bv.y;
                }
                if (resid) {
                    float2 q0 = *(const float2*)(resid + (size_t)r0 * Nd + col);
                    float2 q1 = *(const float2*)(resid + (size_t)r1 * Nd + col);
                    v0.x += q0.x; v0.y += q0.y; v1.x += q1.x; v1.y += q1.y;
                }
                if (do_relu) {
                    v0.x = fmaxf(v0.x, 0.f); v0.y = fmaxf(v0.y, 0.f);
                    v1.x = fmaxf(v1.x, 0.f); v1.y = fmaxf(v1.y, 0.f);
                }
                if (out_tf32) {
                    v0.x = ftf32(v0.x); v0.y = ftf32(v0.y);
                    v1.x = ftf32(v1.x); v1.y = ftf32(v1.y);
                }
                *(float2*)(Cg + (size_t)r0 * Nd + col) = v0;
                *(float2*)(Cg + (size_t)r1 * Nd + col) = v1;
            }
        }
    }
}

// ---------------- flash-style causal attention (R5; output tf32-rounded) --------
#define ALD 68
#define ATTN_SMEM ((128 + 64 + 64) * ALD * 4)

__global__ __launch_bounds__(256)
void k_attn(const float* __restrict__ Qg, const float* __restrict__ Kg,
            const float* __restrict__ Vg, float* __restrict__ attn_out) {
    extern __shared__ float sm[];
    float* Qs = sm;
    float* Ks = Qs + 128 * ALD;
    float* Vs = Ks + 64 * ALD;

    int hb = blockIdx.y;
    int qt = blockIdx.x;
    int h = hb / B, b = hb - h * B;
    int q0 = qt * 128;
    int tid = threadIdx.x;
    int lane = tid & 31;

    const float4* Q4 = (const float4*)(Qg + ((size_t)hb * S + q0) * A);
#pragma unroll
    for (int i = tid; i < 128 * 16; i += 256) {
        int r = i >> 4, c = i & 15;
        *(float4*)&Qs[r * ALD + c * 4] = Q4[i];
    }

    int r = tid >> 2;
    int g = tid & 3;
    int cbase = g * 16;
    float m0 = -INFINITY, l0 = 0.f, m1 = -INFINITY, l1 = 0.f;
    float acc0[16], acc1[16];
#pragma unroll
    for (int i = 0; i < 16; i++) { acc0[i] = 0.f; acc1[i] = 0.f; }

    int ntl = 2 * qt + 2;
    int qi0 = q0 + r, qi1 = q0 + r + 64;
    const float scale = 0.03125f;

    for (int t = 0; t < ntl; t++) {
        int k0 = t * 64;
        __syncthreads();
        const float4* K4 = (const float4*)(Kg + ((size_t)hb * S + k0) * A);
        const float4* V4 = (const float4*)(Vg + ((size_t)hb * S + k0) * A);
#pragma unroll
        for (int i = tid; i < 64 * 16; i += 256) {
            int rr = i >> 4, cc = i & 15;
            *(float4*)&Ks[rr * ALD + cc * 4] = K4[i];
            *(float4*)&Vs[rr * ALD + cc * 4] = V4[i];
        }
        __syncthreads();

        float sv0[16], sv1[16];
#pragma unroll
        for (int i = 0; i < 16; i++) { sv0[i] = 0.f; sv1[i] = 0.f; }
        for (int kc = 0; kc < 16; kc++) {
            float4 qa = *(const float4*)&Qs[r * ALD + kc * 4];
            float4 qb = *(const float4*)&Qs[(r + 64) * ALD + kc * 4];
#pragma unroll
            for (int i = 0; i < 16; i++) {
                float4 k4 = *(const float4*)&Ks[(cbase + i) * ALD + kc * 4];
                sv0[i] += qa.x * k4.x + qa.y * k4.y + qa.z * k4.z + qa.w * k4.w;
                sv1[i] += qb.x * k4.x + qb.y * k4.y + qb.z * k4.z + qb.w * k4.w;
            }
        }

        float ml0 = -INFINITY, ml1 = -INFINITY;
#pragma unroll
        for (int i = 0; i < 16; i++) {
            int kidx = k0 + cbase + i;
            sv0[i] = (kidx <= qi0) ? sv0[i] * scale : -INFINITY;
            sv1[i] = (kidx <= qi1) ? sv1[i] * scale : -INFINITY;
            ml0 = fmaxf(ml0, sv0[i]);
            ml1 = fmaxf(ml1, sv1[i]);
        }
        ml0 = fmaxf(ml0, __shfl_xor_sync(0xffffffff, ml0, 1));
        ml0 = fmaxf(ml0, __shfl_xor_sync(0xffffffff, ml0, 2));
        ml1 = fmaxf(ml1, __shfl_xor_sync(0xffffffff, ml1, 1));
        ml1 = fmaxf(ml1, __shfl_xor_sync(0xffffffff, ml1, 2));

        float mn0 = fmaxf(m0, ml0), mn1 = fmaxf(m1, ml1);
        float al0 = __expf(m0 - mn0), al1 = __expf(m1 - mn1);

        float p0[16], p1[16];
        float ll0 = 0.f, ll1 = 0.f;
#pragma unroll
        for (int i = 0; i < 16; i++) {
            p0[i] = __expf(sv0[i] - mn0); ll0 += p0[i];
            p1[i] = __expf(sv1[i] - mn1); ll1 += p1[i];
        }
        ll0 += __shfl_xor_sync(0xffffffff, ll0, 1);
        ll0 += __shfl_xor_sync(0xffffffff, ll0, 2);
        ll1 += __shfl_xor_sync(0xffffffff, ll1, 1);
        ll1 += __shfl_xor_sync(0xffffffff, ll1, 2);
        l0 = l0 * al0 + ll0;  m0 = mn0;
        l1 = l1 * al1 + ll1;  m1 = mn1;
#pragma unroll
        for (int i = 0; i < 16; i++) { acc0[i] *= al0; acc1[i] *= al1; }

#pragma unroll
        for (int gp = 0; gp < 4; gp++) {
            int src = (lane & 28) | gp;
#pragma unroll
            for (int i = 0; i < 16; i++) {
                float pv0 = __shfl_sync(0xffffffff, p0[i], src);
                float pv1 = __shfl_sync(0xffffffff, p1[i], src);
                const float* vrow = &Vs[(gp * 16 + i) * ALD + cbase];
                float4 v0 = *(const float4*)(vrow + 0);
                float4 v1 = *(const float4*)(vrow + 4);
                float4 v2 = *(const float4*)(vrow + 8);
                float4 v3 = *(const float4*)(vrow + 12);
                acc0[0]  += pv0 * v0.x; acc0[1]  += pv0 * v0.y;
                acc0[2]  += pv0 * v0.z; acc0[3]  += pv0 * v0.w;
                acc0[4]  += pv0 * v1.x; acc0[5]  += pv0 * v1.y;
                acc0[6]  += pv0 * v1.z; acc0[7]  += pv0 * v1.w;
                acc0[8]  += pv0 * v2.x; acc0[9]  += pv0 * v2.y;
                acc0[10] += pv0 * v2.z; acc0[11] += pv0 * v2.w;
                acc0[12] += pv0 * v3.x; acc0[13] += pv0 * v3.y;
                acc0[14] += pv0 * v3.z; acc0[15] += pv0 * v3.w;
                acc1[0]  += pv1 * v0.x; acc1[1]  += pv1 * v0.y;
                acc1[2]  += pv1 * v0.z; acc1[3]  += pv1 * v0.w;
                acc1[4]  += pv1 * v1.x; acc1[5]  += pv1 * v1.y;
                acc1[6]  += pv1 * v1.z; acc1[7]  += pv1 * v1.w;
                acc1[8]  += pv1 * v2.x; acc1[9]  += pv1 * v2.y;
                acc1[10] += pv1 * v2.z; acc1[11] += pv1 * v2.w;
                acc1[12] += pv1 * v3.x; acc1[13] += pv1 * v3.y;
                acc1[14] += pv1 * v3.z; acc1[15] += pv1 * v3.w;
            }
        }
    }

    float il0 = 1.f / l0, il1 = 1.f / l1;
    int row0 = b * S + q0 + r;
    int row1 = row0 + 64;
    float* op0 = attn_out + (size_t)row0 * E + h * A + cbase;
    float* op1 = attn_out + (size_t)row1 * E + h * A + cbase;
#pragma unroll
    for (int i = 0; i < 16; i += 4) {
        float4 o0, o1;
        o0.x = ftf32(acc0[i+0]*il0); o0.y = ftf32(acc0[i+1]*il0);
        o0.z = ftf32(acc0[i+2]*il0); o0.w = ftf32(acc0[i+3]*il0);
        o1.x = ftf32(acc1[i+0]*il1); o1.y = ftf32(acc1[i+1]*il1);
        o1.z = ftf32(acc1[i+2]*il1); o1.w = ftf32(acc1[i+3]*il1);
        *(float4*)(op0 + i) = o0;
        *(float4*)(op1 + i) = o1;
    }
}

// ---------------- LayerNorm (optional tf32 second output) -----------------------
__global__ __launch_bounds__(256)
void k_ln(const float* __restrict__ a, const float* __restrict__ b,
          const float* __restrict__ gg, const float* __restrict__ bb,
          float* __restrict__ o, float* __restrict__ o32) {
    __shared__ float red[16];
    __shared__ float s_mu, s_rstd;
    int row = blockIdx.x;
    int t = threadIdx.x;
    float4 x = ((const float4*)(a + (size_t)row * E))[t];
    if (b) {
        float4 y = ((const float4*)(b + (size_t)row * E))[t];
        x.x += y.x; x.y += y.y; x.z += y.z; x.w += y.w;
    }
    float sum = x.x + x.y + x.z + x.w;
    float sq  = x.x*x.x + x.y*x.y + x.z*x.z + x.w*x.w;
#pragma unroll
    for (int off = 16; off; off >>= 1) {
        sum += __shfl_xor_sync(0xffffffff, sum, off);
        sq  += __shfl_xor_sync(0xffffffff, sq,  off);
    }
    if ((t & 31) == 0) { red[t >> 5] = sum; red[8 + (t >> 5)] = sq; }
    __syncthreads();
    if (t == 0) {
        float ts = 0.f, tq = 0.f;
#pragma unroll
        for (int i = 0; i < 8; i++) { ts += red[i]; tq += red[8 + i]; }
        float mu = ts * (1.f / E);
        float var = tq * (1.f / E) - mu * mu;
        s_mu = mu; s_rstd = rsqrtf(var + 1e-5f);
    }
    __syncthreads();
    float mu = s_mu, rstd = s_rstd;
    float4 g4 = ((const float4*)gg)[t];
    float4 b4 = ((const float4*)bb)[t];
    float4 rr;
    rr.x = (x.x - mu) * rstd * g4.x + b4.x;
    rr.y = (x.y - mu) * rstd * g4.y + b4.y;
    rr.z = (x.z - mu) * rstd * g4.z + b4.z;
    rr.w = (x.w - mu) * rstd * g4.w + b4.w;
    ((float4*)(o + (size_t)row * E))[t] = rr;
    if (o32) ((float4*)(o32 + (size_t)row * E))[t] = ftf32_4(rr);
}

// ---------------- launch ----------------------------------------------------------
extern "C" void kernel_launch(void* const* d_in, const int* in_sizes, int n_in,
                              void* d_out, int out_size) {
    const float* emb    = (const float*)d_in[0];
    const float* pos    = (const float*)d_in[1];
    const float* Wq     = (const float*)d_in[2];
    const float* Wk     = (const float*)d_in[3];
    const float* Wv     = (const float*)d_in[4];
    const float* Wproj  = (const float*)d_in[5];
    const float* W1     = (const float*)d_in[6];
    const float* b1     = (const float*)d_in[7];
    const float* W2     = (const float*)d_in[8];
    const float* b2     = (const float*)d_in[9];
    const float* gattn  = (const float*)d_in[10];
    const float* beattn = (const float*)d_in[11];
    const float* gffn   = (const float*)d_in[12];
    const float* beffn  = (const float*)d_in[13];
    const float* gout   = (const float*)d_in[14];
    const float* beout  = (const float*)d_in[15];

    float* out  = (float*)d_out;
    float* Kout = out + (size_t)M * E;
    float* Vout = out + (size_t)2 * M * E;

    float *px, *px32, *pw, *pwp, *pw1, *pw2, *pqkv, *pq, *pattn;
    float *pmha, *pmha32, *phid, *pff, *pffout;
    cudaGetSymbolAddress((void**)&px,    g_x);
    cudaGetSymbolAddress((void**)&px32,  g_x32);
    cudaGetSymbolAddress((void**)&pw,    g_wqkv32);
    cudaGetSymbolAddress((void**)&pwp,   g_wp32);
    cudaGetSymbolAddress((void**)&pw1,   g_w132);
    cudaGetSymbolAddress((void**)&pw2,   g_w232);
    cudaGetSymbolAddress((void**)&pqkv,  g_qkv);
    cudaGetSymbolAddress((void**)&pq,    g_q);
    cudaGetSymbolAddress((void**)&pattn, g_attn);
    cudaGetSymbolAddress((void**)&pmha,  g_mha);
    cudaGetSymbolAddress((void**)&pmha32,g_mha32);
    cudaGetSymbolAddress((void**)&phid,  g_hidden);
    cudaGetSymbolAddress((void**)&pff,   g_ff);
    cudaGetSymbolAddress((void**)&pffout,g_ffout);

    cudaFuncSetAttribute(k_attn, cudaFuncAttributeMaxDynamicSharedMemorySize,
                         ATTN_SMEM);
    cudaFuncSetAttribute(k_gemm_tc, cudaFuncAttributeMaxDynamicSharedMemorySize,
                         GEMM_SMEM);

    // 1: x = emb + pos (+ tf32 copy)
    k_add<<<(M * E / 4) / 256, 256>>>((const float4*)emb, (const float4*)pos,
                                      (float4*)px, (float4*)px32);
    // 2: fused tf32 QKV weight
    k_wqkv<<<(3 * E * E) / 256, 256>>>(Wq, Wk, Wv, pw);
    // 3: tf32 convert other weights
    k_wcvt<<<(WP4 + 2 * W14) / 256, 256>>>((const float4*)Wproj, (const float4*)W1,
                                           (const float4*)W2, (float4*)pwp,
                                           (float4*)pw1, (float4*)pw2);
    // 4: QKV GEMM -> Q scratch + K/V d_out  (profiled slot)
    k_gemm_tc<<<dim3(NQKV/128, M/128), 256, GEMM_SMEM>>>(
        px32, pw, nullptr, NQKV, E, nullptr, nullptr, 0, 0, 1, pq, Kout, Vout);
    // 5: attention
    k_attn<<<dim3(S/128, H*B), 256, ATTN_SMEM>>>(pq, Kout, Vout, pattn);
    // 6: proj + residual(x full)
    k_gemm_tc<<<dim3(E/128, M/128), 256, GEMM_SMEM>>>(
        pattn, pwp, pqkv, E, E, nullptr, px, 0, 0, 0, nullptr, nullptr, nullptr);
    // 7: LN -> mha (full + tf32)
    k_ln<<<M, 256>>>(pqkv, nullptr, gattn, beattn, pmha, pmha32);
    // 8: FFN1 (+b1, tf32-rounded output)
    k_gemm_tc<<<dim3(FFD/128, M/128), 256, GEMM_SMEM>>>(
        pmha32, pw1, phid, FFD, E, b1, nullptr, 0, 1, 0, nullptr, nullptr, nullptr);
    // 9: FFN2 (+b2, relu)
    k_gemm_tc<<<dim3(E/128, M/128), 256, GEMM_SMEM>>>(
        phid, pw2, pff, E, FFD, b2, nullptr, 1, 0, 0, nullptr, nullptr, nullptr);
    // 10/11: LNs
    k_ln<<<M, 256>>>(pmha, pff, gffn, beffn, pffout, nullptr);
    k_ln<<<M, 256>>>(pmha, pffout, gout, beout, out, nullptr);
}

// round 9
// speedup vs baseline: 6.4046x; 2.9355x over previous
#include <cuda_runtime.h>
#include <math.h>
#include <stdint.h>

// Problem constants
#define E   1024
#define A   64
#define H   16
#define FFD 4096
#define B   2
#define S   2048
#define M   (B*S)
#define NQKV (3*E)

// ---------------- scratch (device globals) -----------------------------------
__device__ float g_x[M*E];           // full-precision x (residual)
__device__ float g_x32[M*E];         // tf32-rounded x (GEMM A)
__device__ float g_wqkv32[E*NQKV];   // fused tf32 [E][3E]
__device__ float g_wp32[E*E];        // tf32 Wproj [K][N]
__device__ float g_w132[E*FFD];      // tf32 W1
__device__ float g_w232[FFD*E];      // tf32 W2
__device__ float g_qkv[M*E];         // proj output scratch
__device__ float g_q[H*B*S*A];       // tf32 Q [hb][s][a]
__device__ float g_kt[H*B*A*S];      // tf32 K^T [hb][a][s]
__device__ float g_attn[M*E];        // tf32-rounded attention out
__device__ float g_mha[M*E];         // full mha (residuals)
__device__ float g_mha32[M*E];       // tf32 mha (FFN1 A)
__device__ float g_hidden[M*FFD];    // tf32-rounded hidden
__device__ float g_ff[M*E];
__device__ float g_ffout[M*E];

// ---------------- helpers -------------------------------------------------------
__device__ __forceinline__ float ftf32(float x) {
    float y;
    asm("cvt.rna.tf32.f32 %0, %1;" : "=f"(y) : "f"(x));
    return y;
}
__device__ __forceinline__ float4 ftf32_4(float4 v) {
    v.x = ftf32(v.x); v.y = ftf32(v.y); v.z = ftf32(v.z); v.w = ftf32(v.w);
    return v;
}
__device__ __forceinline__ uint32_t smem_u32(const void* p) {
    uint32_t r;
    asm("{ .reg .u64 t; cvta.to.shared.u64 t, %1; cvt.u32.u64 %0, t; }"
        : "=r"(r) : "l"(p));
    return r;
}
#define CP16(dst, src) \
    asm volatile("cp.async.cg.shared.global [%0], [%1], 16;" \
                 :: "r"(dst), "l"(src) : "memory")
#define CP_COMMIT() asm volatile("cp.async.commit_group;" ::: "memory")
#define CP_WAIT(n)  asm volatile("cp.async.wait_group %0;" :: "n"(n) : "memory")
#define MMA_TF32(d, a0,a1,a2,a3, b0,b1)                                       \
    asm volatile(                                                             \
        "mma.sync.aligned.m16n8k8.row.col.f32.tf32.tf32.f32 "                 \
        "{%0,%1,%2,%3}, {%4,%5,%6,%7}, {%8,%9}, {%0,%1,%2,%3};"               \
        : "+f"((d)[0]), "+f"((d)[1]), "+f"((d)[2]), "+f"((d)[3])              \
        : "r"(a0), "r"(a1), "r"(a2), "r"(a3), "r"(b0), "r"(b1))
#define FAU(x) __float_as_uint(x)

// ---------------- x = emb + pos (full + tf32 copy) ------------------------------
__global__ void k_add(const float4* __restrict__ a, const float4* __restrict__ b,
                      float4* __restrict__ o, float4* __restrict__ o32) {
    int i = blockIdx.x * blockDim.x + threadIdx.x;
    float4 x = a[i], y = b[i];
    x.x += y.x; x.y += y.y; x.z += y.z; x.w += y.w;
    o[i] = x;
    o32[i] = ftf32_4(x);
}

// ---------------- fuse Wq/Wk/Wv [H,E,A] -> tf32 [E, 3E] -------------------------
__global__ void k_wqkv(const float* __restrict__ Wq, const float* __restrict__ Wk,
                       const float* __restrict__ Wv, float* __restrict__ out) {
    int idx = blockIdx.x * blockDim.x + threadIdx.x;
    int qkv = idx / (E*E);
    int rem = idx - qkv * (E*E);
    int h = rem / (E*A);
    int ea = rem - h * (E*A);
    int e = ea / A;
    int a = ea - e * A;
    const float* W = (qkv == 0) ? Wq : (qkv == 1) ? Wk : Wv;
    out[(size_t)e * NQKV + qkv * E + h * A + a] = ftf32(W[rem]);
}

// ---------------- tf32 convert proj/W1/W2 ----------------------------------------
#define WP4 (E*E/4)
#define W14 (E*FFD/4)
__global__ void k_wcvt(const float4* __restrict__ wp, const float4* __restrict__ w1,
                       const float4* __restrict__ w2, float4* __restrict__ op,
                       float4* __restrict__ o1, float4* __restrict__ o2) {
    int i = blockIdx.x * blockDim.x + threadIdx.x;
    if (i < WP4)                op[i] = ftf32_4(wp[i]);
    else if (i < WP4 + W14)     o1[i - WP4] = ftf32_4(w1[i - WP4]);
    else                        o2[i - WP4 - W14] = ftf32_4(w2[i - WP4 - W14]);
}

// ---------------- tf32 mma.sync GEMM, cp.async 3-stage (R8 core) -----------------
#define STG_F 4736
#define GEMM_SMEM (3 * STG_F * 4)

__global__ __launch_bounds__(256, 2)
void k_gemm_tc(const float* __restrict__ Ag, const float* __restrict__ Bg,
               float* __restrict__ Cg, int Nd, int Kd,
               const float* __restrict__ bias, const float* __restrict__ resid,
               int do_relu, int out_tf32, int qkv_mode,
               float* __restrict__ qd, float* __restrict__ kd,
               float* __restrict__ vd, float* __restrict__ ktd) {
    extern __shared__ float smf[];
    uint32_t sb = smem_u32(smf);

    int tid = threadIdx.x;
    int lane = tid & 31, wid = tid >> 5;
    int wm = wid & 1, wn = wid >> 1;
    int gid = lane >> 2, qid = lane & 3;

    const float* Ab = Ag + (size_t)blockIdx.y * 128 * Kd;
    const float* Bb = Bg + blockIdx.x * 128;

    int c1 = tid, c2 = tid + 256;
    int a1r = c1 >> 2, a1o = (c1 & 3) * 16, a1c = (c1 & 3) * 4;
    int a2r = c2 >> 2, a2o = (c2 & 3) * 16, a2c = (c2 & 3) * 4;
    int b1r = c1 >> 5, b1o = (c1 & 31) * 16, b1c = (c1 & 31) * 4;
    int b2r = c2 >> 5, b2o = (c2 & 31) * 16, b2c = (c2 & 31) * 4;

    float acc[4][4][4];
#pragma unroll
    for (int i = 0; i < 4; i++)
#pragma unroll
        for (int j = 0; j < 4; j++)
#pragma unroll
            for (int r = 0; r < 4; r++) acc[i][j][r] = 0.f;

    int nk = Kd >> 4;

#define LOAD_STAGE(s, k0)                                                     \
    do {                                                                      \
        uint32_t A0 = sb + (s) * (STG_F * 4);                                 \
        uint32_t B0 = A0 + 2560 * 4;                                          \
        CP16(A0 + a1r * 80 + a1o, Ab + (size_t)a1r * Kd + (k0) + a1c);        \
        CP16(A0 + a2r * 80 + a2o, Ab + (size_t)a2r * Kd + (k0) + a2c);        \
        CP16(B0 + b1r * 544 + b1o, Bb + (size_t)((k0) + b1r) * Nd + b1c);     \
        CP16(B0 + b2r * 544 + b2o, Bb + (size_t)((k0) + b2r) * Nd + b2c);     \
        CP_COMMIT();                                                          \
    } while (0)

    LOAD_STAGE(0, 0);
    LOAD_STAGE(1, 16);

    int buf = 0;
    for (int kc = 0; kc < nk; kc++) {
        if (kc + 2 < nk) { CP_WAIT(1); } else { CP_WAIT(0); }
        __syncthreads();
        if (kc + 2 < nk) {
            int s = (kc + 2) % 3;
            LOAD_STAGE(s, (kc + 2) * 16);
        }
        const float* As = smf + buf * STG_F;
        const float* Bs = As + 2560;
#pragma unroll
        for (int ks = 0; ks < 16; ks += 8) {
            unsigned af[4][4], bf[4][2];
#pragma unroll
            for (int mi = 0; mi < 4; mi++) {
                int row = wm * 64 + mi * 16 + gid;
                af[mi][0] = FAU(As[row * 20 + ks + qid]);
                af[mi][1] = FAU(As[(row + 8) * 20 + ks + qid]);
                af[mi][2] = FAU(As[row * 20 + ks + qid + 4]);
                af[mi][3] = FAU(As[(row + 8) * 20 + ks + qid + 4]);
            }
#pragma unroll
            for (int ni = 0; ni < 4; ni++) {
                int col = wn * 32 + ni * 8 + gid;
                bf[ni][0] = FAU(Bs[(ks + qid) * 136 + col]);
                bf[ni][1] = FAU(Bs[(ks + qid + 4) * 136 + col]);
            }
#pragma unroll
            for (int mi = 0; mi < 4; mi++)
#pragma unroll
                for (int ni = 0; ni < 4; ni++)
                    MMA_TF32(acc[mi][ni], af[mi][0], af[mi][1], af[mi][2],
                             af[mi][3], bf[ni][0], bf[ni][1]);
        }
        buf = (buf + 1) % 3;
    }
#undef LOAD_STAGE

    // epilogue
    int bn = blockIdx.x * 128;
#pragma unroll
    for (int mi = 0; mi < 4; mi++) {
        int r0 = blockIdx.y * 128 + wm * 64 + mi * 16 + gid;
        int r1 = r0 + 8;
#pragma unroll
        for (int ni = 0; ni < 4; ni++) {
            int col = bn + wn * 32 + ni * 8 + 2 * qid;
            float2 v0 = make_float2(acc[mi][ni][0], acc[mi][ni][1]);
            float2 v1 = make_float2(acc[mi][ni][2], acc[mi][ni][3]);
            if (qkv_mode) {
                int which = col >> 10;
                int cc = col & 1023;
                int hh = cc >> 6, aa = cc & 63;
                int bb = r0 >> 11;
                int s0r = r0 & 2047, s1r = r1 & 2047;
                int hb_ = hh * B + bb;
                size_t d0 = (((size_t)hb_ * S + s0r) * A + aa);
                size_t d1 = (((size_t)hb_ * S + s1r) * A + aa);
                if (which == 0) {
                    v0.x = ftf32(v0.x); v0.y = ftf32(v0.y);
                    v1.x = ftf32(v1.x); v1.y = ftf32(v1.y);
                    *(float2*)(qd + d0) = v0;
                    *(float2*)(qd + d1) = v1;
                } else if (which == 1) {
                    *(float2*)(kd + d0) = v0;
                    *(float2*)(kd + d1) = v1;
                    size_t kt0 = ((size_t)hb_ * A + aa) * S;
                    ktd[kt0 + s0r]     = ftf32(v0.x);
                    ktd[kt0 + S + s0r] = ftf32(v0.y);
                    ktd[kt0 + s1r]     = ftf32(v1.x);
                    ktd[kt0 + S + s1r] = ftf32(v1.y);
                } else {
                    *(float2*)(vd + d0) = v0;
                    *(float2*)(vd + d1) = v1;
                }
            } else {
                if (bias) {
                    float2 bv = *(const float2*)(bias + col);
                    v0.x += bv.x; v0.y += bv.y; v1.x += bv.x; v1.y += bv.y;
                }
                if (resid) {
                    float2 q0 = *(const float2*)(resid + (size_t)r0 * Nd + col);
                    float2 q1 = *(const float2*)(resid + (size_t)r1 * Nd + col);
                    v0.x += q0.x; v0.y += q0.y; v1.x += q1.x; v1.y += q1.y;
                }
                if (do_relu) {
                    v0.x = fmaxf(v0.x, 0.f); v0.y = fmaxf(v0.y, 0.f);
                    v1.x = fmaxf(v1.x, 0.f); v1.y = fmaxf(v1.y, 0.f);
                }
                if (out_tf32) {
                    v0.x = ftf32(v0.x); v0.y = ftf32(v0.y);
                    v1.x = ftf32(v1.x); v1.y = ftf32(v1.y);
                }
                *(float2*)(Cg + (size_t)r0 * Nd + col) = v0;
                *(float2*)(Cg + (size_t)r1 * Nd + col) = v1;
            }
        }
    }
}

// ---------------- tensor-core flash attention ------------------------------------
// CTA = (q-tile 128 rows, hb). 8 warps x 16 rows. K-tiles of 64 keys.
#define QSP 68
#define KTP 72
#define ATT_SMEM ((2 * 128 * QSP + 2 * 64 * KTP) * 4)   // 106496 B

__global__ __launch_bounds__(256, 2)
void k_attn(const float* __restrict__ Qg, const float* __restrict__ Ktg,
            const float* __restrict__ Vg, float* __restrict__ attn_out) {
    extern __shared__ float sm[];
    float* Qs = sm;                       // [128][QSP]
    float* Ps = Qs + 128 * QSP;           // [128][QSP]
    float* Kt = Ps + 128 * QSP;           // [64][KTP]  (dim x key)
    float* Vs = Kt + 64 * KTP;            // [64][KTP]  (key x dim)

    int tid = threadIdx.x, lane = tid & 31, wid = tid >> 5;
    int gid = lane >> 2, qid = lane & 3;
    int hb = blockIdx.y, qt = blockIdx.x;
    int h = hb / B, b = hb - h * B;
    int q0 = qt * 128;

    // Q tile (pre-rounded tf32)
    const float4* Q4 = (const float4*)(Qg + ((size_t)hb * S + q0) * A);
#pragma unroll
    for (int j = 0; j < 8; j++) {
        int i = tid + j * 256;
        int r = i >> 4, c = i & 15;
        *(float4*)&Qs[r * QSP + c * 4] = Q4[i];
    }

    int wr = wid * 16;
    int r0g = q0 + wr + gid, r1g = r0g + 8;
    float m0 = -INFINITY, m1 = -INFINITY, l0 = 0.f, l1 = 0.f;
    float o[8][4];
#pragma unroll
    for (int nt = 0; nt < 8; nt++)
#pragma unroll
        for (int c = 0; c < 4; c++) o[nt][c] = 0.f;

    const float scale = 0.03125f;   // 1/sqrt(E)
    int ntl = 2 * qt + 2;
    const float4* Kt4 = (const float4*)(Ktg + (size_t)hb * A * S);
    const float4* V4g = (const float4*)(Vg + (size_t)hb * S * A);

    for (int t = 0; t < ntl; t++) {
        int k0 = t * 64;
        __syncthreads();
#pragma unroll
        for (int j = 0; j < 4; j++) {
            int i = tid + j * 256;
            int d = i >> 4, q4 = i & 15;
            float4 kv = Kt4[d * (S / 4) + (k0 >> 2) + q4];   // pre-rounded tf32
            *(float4*)&Kt[d * KTP + q4 * 4] = kv;
            float4 vv = V4g[(size_t)(k0 + d) * 16 + q4];     // d == key here
            *(float4*)&Vs[d * KTP + q4 * 4] = ftf32_4(vv);
        }
        __syncthreads();

        if (k0 <= q0 + wr + 15) {
            // ---- QK^T ----
            float sa[8][4];
#pragma unroll
            for (int nt = 0; nt < 8; nt++)
#pragma unroll
                for (int c = 0; c < 4; c++) sa[nt][c] = 0.f;
#pragma unroll
            for (int ks = 0; ks < 64; ks += 8) {
                unsigned a0 = FAU(Qs[(wr + gid) * QSP + ks + qid]);
                unsigned a1 = FAU(Qs[(wr + gid + 8) * QSP + ks + qid]);
                unsigned a2 = FAU(Qs[(wr + gid) * QSP + ks + qid + 4]);
                unsigned a3 = FAU(Qs[(wr + gid + 8) * QSP + ks + qid + 4]);
#pragma unroll
                for (int nt = 0; nt < 8; nt++) {
                    unsigned b0 = FAU(Kt[(ks + qid) * KTP + nt * 8 + gid]);
                    unsigned b1 = FAU(Kt[(ks + qid + 4) * KTP + nt * 8 + gid]);
                    MMA_TF32(sa[nt], a0, a1, a2, a3, b0, b1);
                }
            }
            // ---- scale + mask + online softmax ----
            float mx0 = -INFINITY, mx1 = -INFINITY;
#pragma unroll
            for (int nt = 0; nt < 8; nt++) {
                int colb = k0 + nt * 8 + 2 * qid;
                sa[nt][0] = (colb     <= r0g) ? sa[nt][0] * scale : -INFINITY;
                sa[nt][1] = (colb + 1 <= r0g) ? sa[nt][1] * scale : -INFINITY;
                sa[nt][2] = (colb     <= r1g) ? sa[nt][2] * scale : -INFINITY;
                sa[nt][3] = (colb + 1 <= r1g) ? sa[nt][3] * scale : -INFINITY;
                mx0 = fmaxf(mx0, fmaxf(sa[nt][0], sa[nt][1]));
                mx1 = fmaxf(mx1, fmaxf(sa[nt][2], sa[nt][3]));
            }
            mx0 = fmaxf(mx0, __shfl_xor_sync(0xffffffff, mx0, 1));
            mx0 = fmaxf(mx0, __shfl_xor_sync(0xffffffff, mx0, 2));
            mx1 = fmaxf(mx1, __shfl_xor_sync(0xffffffff, mx1, 1));
            mx1 = fmaxf(mx1, __shfl_xor_sync(0xffffffff, mx1, 2));
            float mn0 = fmaxf(m0, mx0), mn1 = fmaxf(m1, mx1);
            float al0 = __expf(m0 - mn0), al1 = __expf(m1 - mn1);
            float sum0 = 0.f, sum1 = 0.f;
#pragma unroll
            for (int nt = 0; nt < 8; nt++) {
                sa[nt][0] = __expf(sa[nt][0] - mn0); sum0 += sa[nt][0];
                sa[nt][1] = __expf(sa[nt][1] - mn0); sum0 += sa[nt][1];
                sa[nt][2] = __expf(sa[nt][2] - mn1); sum1 += sa[nt][2];
                sa[nt][3] = __expf(sa[nt][3] - mn1); sum1 += sa[nt][3];
            }
            sum0 += __shfl_xor_sync(0xffffffff, sum0, 1);
            sum0 += __shfl_xor_sync(0xffffffff, sum0, 2);
            sum1 += __shfl_xor_sync(0xffffffff, sum1, 1);
            sum1 += __shfl_xor_sync(0xffffffff, sum1, 2);
            l0 = l0 * al0 + sum0;  m0 = mn0;
            l1 = l1 * al1 + sum1;  m1 = mn1;
#pragma unroll
            for (int nt = 0; nt < 8; nt++) {
                o[nt][0] *= al0; o[nt][1] *= al0;
                o[nt][2] *= al1; o[nt][3] *= al1;
            }
            // ---- P -> smem (warp-private rows) ----
#pragma unroll
            for (int nt = 0; nt < 8; nt++) {
                *(float2*)&Ps[(wr + gid) * QSP + nt * 8 + 2 * qid] =
                    make_float2(ftf32(sa[nt][0]), ftf32(sa[nt][1]));
                *(float2*)&Ps[(wr + gid + 8) * QSP + nt * 8 + 2 * qid] =
                    make_float2(ftf32(sa[nt][2]), ftf32(sa[nt][3]));
            }
            __syncwarp();
            // ---- PV ----
#pragma unroll
            for (int ks = 0; ks < 64; ks += 8) {
                unsigned a0 = FAU(Ps[(wr + gid) * QSP + ks + qid]);
                unsigned a1 = FAU(Ps[(wr + gid + 8) * QSP + ks + qid]);
                unsigned a2 = FAU(Ps[(wr + gid) * QSP + ks + qid + 4]);
                unsigned a3 = FAU(Ps[(wr + gid + 8) * QSP + ks + qid + 4]);
#pragma unroll
                for (int nt = 0; nt < 8; nt++) {
                    unsigned b0 = FAU(Vs[(ks + qid) * KTP + nt * 8 + gid]);
                    unsigned b1 = FAU(Vs[(ks + qid + 4) * KTP + nt * 8 + gid]);
                    MMA_TF32(o[nt], a0, a1, a2, a3, b0, b1);
                }
            }
        }
    }

    // epilogue: divide by l, tf32-round (feeds proj GEMM)
    float il0 = 1.f / l0, il1 = 1.f / l1;
    int row0 = b * S + q0 + wr + gid;
    int row1 = row0 + 8;
#pragma unroll
    for (int nt = 0; nt < 8; nt++) {
        int col = h * A + nt * 8 + 2 * qid;
        *(float2*)(attn_out + (size_t)row0 * E + col) =
            make_float2(ftf32(o[nt][0] * il0), ftf32(o[nt][1] * il0));
        *(float2*)(attn_out + (size_t)row1 * E + col) =
            make_float2(ftf32(o[nt][2] * il1), ftf32(o[nt][3] * il1));
    }
}

// ---------------- LayerNorm (optional tf32 second output) -----------------------
__global__ __launch_bounds__(256)
void k_ln(const float* __restrict__ a, const float* __restrict__ b,
          const float* __restrict__ gg, const float* __restrict__ bb,
          float* __restrict__ o, float* __restrict__ o32) {
    __shared__ float red[16];
    __shared__ float s_mu, s_rstd;
    int row = blockIdx.x;
    int t = threadIdx.x;
    float4 x = ((const float4*)(a + (size_t)row * E))[t];
    if (b) {
        float4 y = ((const float4*)(b + (size_t)row * E))[t];
        x.x += y.x; x.y += y.y; x.z += y.z; x.w += y.w;
    }
    float sum = x.x + x.y + x.z + x.w;
    float sq  = x.x*x.x + x.y*x.y + x.z*x.z + x.w*x.w;
#pragma unroll
    for (int off = 16; off; off >>= 1) {
        sum += __shfl_xor_sync(0xffffffff, sum, off);
        sq  += __shfl_xor_sync(0xffffffff, sq,  off);
    }
    if ((t & 31) == 0) { red[t >> 5] = sum; red[8 + (t >> 5)] = sq; }
    __syncthreads();
    if (t == 0) {
        float ts = 0.f, tq = 0.f;
#pragma unroll
        for (int i = 0; i < 8; i++) { ts += red[i]; tq += red[8 + i]; }
        float mu = ts * (1.f / E);
        float var = tq * (1.f / E) - mu * mu;
        s_mu = mu; s_rstd = rsqrtf(var + 1e-5f);
    }
    __syncthreads();
    float mu = s_mu, rstd = s_rstd;
    float4 g4 = ((const float4*)gg)[t];
    float4 b4 = ((const float4*)bb)[t];
    float4 rr;
    rr.x = (x.x - mu) * rstd * g4.x + b4.x;
    rr.y = (x.y - mu) * rstd * g4.y + b4.y;
    rr.z = (x.z - mu) * rstd * g4.z + b4.z;
    rr.w = (x.w - mu) * rstd * g4.w + b4.w;
    ((float4*)(o + (size_t)row * E))[t] = rr;
    if (o32) ((float4*)(o32 + (size_t)row * E))[t] = ftf32_4(rr);
}

// ---------------- launch ----------------------------------------------------------
extern "C" void kernel_launch(void* const* d_in, const int* in_sizes, int n_in,
                              void* d_out, int out_size) {
    const float* emb    = (const float*)d_in[0];
    const float* pos    = (const float*)d_in[1];
    const float* Wq     = (const float*)d_in[2];
    const float* Wk     = (const float*)d_in[3];
    const float* Wv     = (const float*)d_in[4];
    const float* Wproj  = (const float*)d_in[5];
    const float* W1     = (const float*)d_in[6];
    const float* b1     = (const float*)d_in[7];
    const float* W2     = (const float*)d_in[8];
    const float* b2     = (const float*)d_in[9];
    const float* gattn  = (const float*)d_in[10];
    const float* beattn = (const float*)d_in[11];
    const float* gffn   = (const float*)d_in[12];
    const float* beffn  = (const float*)d_in[13];
    const float* gout   = (const float*)d_in[14];
    const float* beout  = (const float*)d_in[15];

    float* out  = (float*)d_out;
    float* Kout = out + (size_t)M * E;
    float* Vout = out + (size_t)2 * M * E;

    float *px, *px32, *pw, *pwp, *pw1, *pw2, *pqkv, *pq, *pkt, *pattn;
    float *pmha, *pmha32, *phid, *pff, *pffout;
    cudaGetSymbolAddress((void**)&px,    g_x);
    cudaGetSymbolAddress((void**)&px32,  g_x32);
    cudaGetSymbolAddress((void**)&pw,    g_wqkv32);
    cudaGetSymbolAddress((void**)&pwp,   g_wp32);
    cudaGetSymbolAddress((void**)&pw1,   g_w132);
    cudaGetSymbolAddress((void**)&pw2,   g_w232);
    cudaGetSymbolAddress((void**)&pqkv,  g_qkv);
    cudaGetSymbolAddress((void**)&pq,    g_q);
    cudaGetSymbolAddress((void**)&pkt,   g_kt);
    cudaGetSymbolAddress((void**)&pattn, g_attn);
    cudaGetSymbolAddress((void**)&pmha,  g_mha);
    cudaGetSymbolAddress((void**)&pmha32,g_mha32);
    cudaGetSymbolAddress((void**)&phid,  g_hidden);
    cudaGetSymbolAddress((void**)&pff,   g_ff);
    cudaGetSymbolAddress((void**)&pffout,g_ffout);

    cudaFuncSetAttribute(k_attn, cudaFuncAttributeMaxDynamicSharedMemorySize,
                         ATT_SMEM);
    cudaFuncSetAttribute(k_gemm_tc, cudaFuncAttributeMaxDynamicSharedMemorySize,
                         GEMM_SMEM);

    // 1: x = emb + pos (+ tf32 copy)
    k_add<<<(M * E / 4) / 256, 256>>>((const float4*)emb, (const float4*)pos,
                                      (float4*)px, (float4*)px32);
    // 2: fused tf32 QKV weight
    k_wqkv<<<(3 * E * E) / 256, 256>>>(Wq, Wk, Wv, pw);
    // 3: tf32 convert other weights
    k_wcvt<<<(WP4 + 2 * W14) / 256, 256>>>((const float4*)Wproj, (const float4*)W1,
                                           (const float4*)W2, (float4*)pwp,
                                           (float4*)pw1, (float4*)pw2);
    // 4: QKV GEMM -> Q(tf32) + K/V d_out + K^T(tf32)
    k_gemm_tc<<<dim3(NQKV/128, M/128), 256, GEMM_SMEM>>>(
        px32, pw, nullptr, NQKV, E, nullptr, nullptr, 0, 0, 1, pq, Kout, Vout, pkt);
    // 5: tensor-core flash attention
    k_attn<<<dim3(S/128, H*B), 256, ATT_SMEM>>>(pq, pkt, Vout, pattn);
    // 6: proj + residual(x full)
    k_gemm_tc<<<dim3(E/128, M/128), 256, GEMM_SMEM>>>(
        pattn, pwp, pqkv, E, E, nullptr, px, 0, 0, 0, nullptr, nullptr, nullptr, nullptr);
    // 7: LN -> mha (full + tf32)
    k_ln<<<M, 256>>>(pqkv, nullptr, gattn, beattn, pmha, pmha32);
    // 8: FFN1 (+b1, tf32-rounded output)
    k_gemm_tc<<<dim3(FFD/128, M/128), 256, GEMM_SMEM>>>(
        pmha32, pw1, phid, FFD, E, b1, nullptr, 0, 1, 0, nullptr, nullptr, nullptr, nullptr);
    // 9: FFN2 (+b2, relu)
    k_gemm_tc<<<dim3(E/128, M/128), 256, GEMM_SMEM>>>(
        phid, pw2, pff, E, FFD, b2, nullptr, 1, 0, 0, nullptr, nullptr, nullptr, nullptr);
    // 10/11: LNs
    k_ln<<<M, 256>>>(pmha, pff, gffn, beffn, pffout, nullptr);
    k_ln<<<M, 256>>>(pmha, pffout, gout, beout, out, nullptr);
}